// round 1
// baseline (speedup 1.0000x reference)
#include <cuda_runtime.h>
#include <math.h>

#define HEADS 16
#define DH 64
#define NB 4
#define NSEQ 1024
#define DIMIN 1024
#define BH (NB * HEADS)          // 64
#define QP_LD 1056               // padded row stride for qp (1025 cols)
#define ATT_SCALE 0.125f         // 64^-0.5

// ---- scratch (device globals; no allocations allowed) ----
__device__ float g_Q[(size_t)BH * NSEQ * DH];          // [b][h][n][d]  16 MB
__device__ float g_K[(size_t)BH * NSEQ * DH];          // 16 MB
__device__ float g_V[(size_t)BH * NSEQ * DH];          // 16 MB
__device__ float g_QP[(size_t)BH * NSEQ * QP_LD];      // [bh*n][1056]  277 MB

// ============================================================================
// Projection GEMM: out[((b*16+h)*1024 + i)*64 + dd] = sum_k X[b*1024+i][k] * W[k][col_off + h*64 + dd]
// 128x128 tile, K-chunk 8, 256 threads, 8x8 microtile. target: 0=Q 1=K 2=V
// ============================================================================
__global__ __launch_bounds__(256, 2)
void proj_kernel(const float* __restrict__ X, const float* __restrict__ W,
                 int ldw, int col_off, int target)
{
    __shared__ float Ast[8][128];   // k-major A tile
    __shared__ float Bs[8][128];    // B tile

    float* out = (target == 0) ? g_Q : (target == 1) ? g_K : g_V;

    const int tid = threadIdx.x;
    const int m0 = blockIdx.y * 128;
    const int n0 = blockIdx.x * 128;
    const int ty = tid >> 4, tx = tid & 15;

    float acc[8][8];
#pragma unroll
    for (int r = 0; r < 8; r++)
#pragma unroll
        for (int s = 0; s < 8; s++) acc[r][s] = 0.f;

    const int arow = tid >> 1, akc = (tid & 1) * 4;
    const int bkk = tid >> 5, bcol = (tid & 31) * 4;

    for (int k0 = 0; k0 < DIMIN; k0 += 8) {
        float4 av = *(const float4*)(X + (size_t)(m0 + arow) * DIMIN + k0 + akc);
        Ast[akc + 0][arow] = av.x; Ast[akc + 1][arow] = av.y;
        Ast[akc + 2][arow] = av.z; Ast[akc + 3][arow] = av.w;
        float4 bv = *(const float4*)(W + (size_t)(k0 + bkk) * ldw + col_off + n0 + bcol);
        *(float4*)&Bs[bkk][bcol] = bv;
        __syncthreads();
#pragma unroll
        for (int kk = 0; kk < 8; kk++) {
            float4 a0 = *(float4*)&Ast[kk][ty * 8];
            float4 a1 = *(float4*)&Ast[kk][ty * 8 + 4];
            float4 b0 = *(float4*)&Bs[kk][tx * 8];
            float4 b1 = *(float4*)&Bs[kk][tx * 8 + 4];
            float a[8] = {a0.x, a0.y, a0.z, a0.w, a1.x, a1.y, a1.z, a1.w};
            float b[8] = {b0.x, b0.y, b0.z, b0.w, b1.x, b1.y, b1.z, b1.w};
#pragma unroll
            for (int r = 0; r < 8; r++)
#pragma unroll
                for (int s = 0; s < 8; s++) acc[r][s] += a[r] * b[s];
        }
        __syncthreads();
    }

#pragma unroll
    for (int r = 0; r < 8; r++) {
        int gm = m0 + ty * 8 + r;
        int b = gm >> 10, i = gm & 1023;
#pragma unroll
        for (int s4 = 0; s4 < 2; s4++) {
            int gc = n0 + tx * 8 + s4 * 4;
            int h = gc >> 6, dd = gc & 63;
            float4 v = make_float4(acc[r][s4 * 4 + 0], acc[r][s4 * 4 + 1],
                                   acc[r][s4 * 4 + 2], acc[r][s4 * 4 + 3]);
            *(float4*)(out + ((size_t)((b * HEADS + h) * NSEQ + i)) * DH + dd) = v;
        }
    }
}

// ============================================================================
// qp GEMM: g_QP[m][p] = sum_d g_Q[m][d] * PE[p][d];  M=65536, N=1025, K=64
// ============================================================================
__global__ __launch_bounds__(256, 2)
void qp_kernel(const float* __restrict__ PE)
{
    __shared__ float Ast[8][128];   // d-major Q tile
    __shared__ float Bst[8][128];   // d-major PE tile

    const int tid = threadIdx.x;
    const int m0 = blockIdx.y * 128;
    const int p0 = blockIdx.x * 128;
    const int ty = tid >> 4, tx = tid & 15;

    float acc[8][8];
#pragma unroll
    for (int r = 0; r < 8; r++)
#pragma unroll
        for (int s = 0; s < 8; s++) acc[r][s] = 0.f;

    const int arow = tid >> 1, akc = (tid & 1) * 4;
    const int bp = tid >> 1, bdc = (tid & 1) * 4;

    for (int k0 = 0; k0 < DH; k0 += 8) {
        float4 av = *(const float4*)(g_Q + (size_t)(m0 + arow) * DH + k0 + akc);
        Ast[akc + 0][arow] = av.x; Ast[akc + 1][arow] = av.y;
        Ast[akc + 2][arow] = av.z; Ast[akc + 3][arow] = av.w;
        float4 bv = make_float4(0.f, 0.f, 0.f, 0.f);
        if (p0 + bp < 1025)
            bv = *(const float4*)(PE + (size_t)(p0 + bp) * DH + k0 + bdc);
        Bst[bdc + 0][bp] = bv.x; Bst[bdc + 1][bp] = bv.y;
        Bst[bdc + 2][bp] = bv.z; Bst[bdc + 3][bp] = bv.w;
        __syncthreads();
#pragma unroll
        for (int kk = 0; kk < 8; kk++) {
            float4 a0 = *(float4*)&Ast[kk][ty * 8];
            float4 a1 = *(float4*)&Ast[kk][ty * 8 + 4];
            float4 b0 = *(float4*)&Bst[kk][tx * 8];
            float4 b1 = *(float4*)&Bst[kk][tx * 8 + 4];
            float a[8] = {a0.x, a0.y, a0.z, a0.w, a1.x, a1.y, a1.z, a1.w};
            float b[8] = {b0.x, b0.y, b0.z, b0.w, b1.x, b1.y, b1.z, b1.w};
#pragma unroll
            for (int r = 0; r < 8; r++)
#pragma unroll
                for (int s = 0; s < 8; s++) acc[r][s] += a[r] * b[s];
        }
        __syncthreads();
    }

#pragma unroll
    for (int r = 0; r < 8; r++) {
        int gm = m0 + ty * 8 + r;
        size_t rb = (size_t)gm * QP_LD;
#pragma unroll
        for (int s = 0; s < 8; s++) {
            int gp = p0 + tx * 8 + s;
            if (gp < 1025) g_QP[rb + gp] = acc[r][s];
        }
    }
}

// ============================================================================
// Fused flash attention with qp-gather bias.
// Block = (bh, q-tile of 128). Key tiles of 128. 256 threads.
// ============================================================================
#define LD132 132
#define SMEM_ATTN ((2 * 64 * LD132 + 128 * 64 + 128 * 128 + 3 * 128) * 4)

__global__ __launch_bounds__(256, 1)
void attn_kernel(float* __restrict__ out)
{
    extern __shared__ float sm[];
    float* Qst = sm;                       // [64 d][132]   (d-major, 128 rows used)
    float* Kst = Qst + 64 * LD132;         // [64 d][132]
    float* Vs  = Kst + 64 * LD132;         // [128 j][64 c]
    float* Ss  = Vs + 128 * 64;            // [128 i][128 j]
    float* s_m = Ss + 128 * 128;           // [128]
    float* s_l = s_m + 128;
    float* s_r = s_l + 128;

    const int tid = threadIdx.x;
    const int bh = blockIdx.x;
    const int qt = blockIdx.y;
    const size_t hb = (size_t)bh * NSEQ * DH;

    // load Q tile transposed into Qst[d][l]
#pragma unroll
    for (int rep = 0; rep < 8; rep++) {
        int idx = tid + rep * 256;          // float4 index into [128][16]
        int l = idx >> 4, d4 = (idx & 15) * 4;
        float4 v = *(const float4*)(g_Q + hb + (size_t)(qt * 128 + l) * DH + d4);
        Qst[(d4 + 0) * LD132 + l] = v.x;
        Qst[(d4 + 1) * LD132 + l] = v.y;
        Qst[(d4 + 2) * LD132 + l] = v.z;
        Qst[(d4 + 3) * LD132 + l] = v.w;
    }
    if (tid < 128) { s_m[tid] = -INFINITY; s_l[tid] = 0.f; }

    const int ty = tid >> 4, tx = tid & 15;   // phase1: rows ty*8.., cols tx*8..
                                              // phase2: rows ty*8.., cols tx*4..
    float o[8][4];
#pragma unroll
    for (int r = 0; r < 8; r++)
#pragma unroll
        for (int c = 0; c < 4; c++) o[r][c] = 0.f;

    __syncthreads();

    for (int kt = 0; kt < 8; kt++) {
        // ---- load K (transposed) and V tiles ----
#pragma unroll
        for (int rep = 0; rep < 8; rep++) {
            int idx = tid + rep * 256;
            int l = idx >> 4, d4 = (idx & 15) * 4;
            size_t goff = hb + (size_t)(kt * 128 + l) * DH + d4;
            float4 kv = *(const float4*)(g_K + goff);
            Kst[(d4 + 0) * LD132 + l] = kv.x;
            Kst[(d4 + 1) * LD132 + l] = kv.y;
            Kst[(d4 + 2) * LD132 + l] = kv.z;
            Kst[(d4 + 3) * LD132 + l] = kv.w;
            float4 vv = *(const float4*)(g_V + goff);
            *(float4*)&Vs[l * 64 + d4] = vv;
        }
        __syncthreads();

        // ---- phase 1: S = Q K^T ----
        float c[8][8];
#pragma unroll
        for (int r = 0; r < 8; r++)
#pragma unroll
            for (int s = 0; s < 8; s++) c[r][s] = 0.f;

#pragma unroll 8
        for (int kk = 0; kk < 64; kk++) {
            float4 a0 = *(float4*)&Qst[kk * LD132 + ty * 8];
            float4 a1 = *(float4*)&Qst[kk * LD132 + ty * 8 + 4];
            float4 b0 = *(float4*)&Kst[kk * LD132 + tx * 8];
            float4 b1 = *(float4*)&Kst[kk * LD132 + tx * 8 + 4];
            float a[8] = {a0.x, a0.y, a0.z, a0.w, a1.x, a1.y, a1.z, a1.w};
            float b[8] = {b0.x, b0.y, b0.z, b0.w, b1.x, b1.y, b1.z, b1.w};
#pragma unroll
            for (int r = 0; r < 8; r++)
#pragma unroll
                for (int s = 0; s < 8; s++) c[r][s] += a[r] * b[s];
        }

        // ---- bias gather + scale, write S tile ----
#pragma unroll
        for (int r = 0; r < 8; r++) {
            int qi = qt * 128 + ty * 8 + r;
            const float* qpr = g_QP + ((size_t)bh * NSEQ + qi) * QP_LD;
#pragma unroll
            for (int s = 0; s < 8; s++) {
                int j = kt * 128 + tx * 8 + s;
                int dlt = qi - j;
                dlt = dlt > 512 ? 512 : (dlt < -512 ? -512 : dlt);
                float val = (c[r][s] + qpr[dlt + 512]) * ATT_SCALE;
                Ss[(ty * 8 + r) * 128 + tx * 8 + s] = val;
            }
        }
        __syncthreads();

        // ---- online softmax (one thread per row, diagonal access) ----
        if (tid < 128) {
            const int i = tid;
            float mold = s_m[i];
            float mnew = mold;
#pragma unroll 8
            for (int jj = 0; jj < 128; jj++) {
                float v = Ss[i * 128 + ((jj + i) & 127)];
                mnew = fmaxf(mnew, v);
            }
            float rsc = __expf(mold - mnew);
            float lsum = 0.f;
#pragma unroll 8
            for (int jj = 0; jj < 128; jj++) {
                int j = (jj + i) & 127;
                float p = __expf(Ss[i * 128 + j] - mnew);
                Ss[i * 128 + j] = p;
                lsum += p;
            }
            s_l[i] = s_l[i] * rsc + lsum;
            s_m[i] = mnew;
            s_r[i] = rsc;
        }
        __syncthreads();

        // ---- phase 2: O = O * r + P @ V ----
#pragma unroll
        for (int r = 0; r < 8; r++) {
            float rsc = s_r[ty * 8 + r];
#pragma unroll
            for (int cc = 0; cc < 4; cc++) o[r][cc] *= rsc;
        }
#pragma unroll 8
        for (int j = 0; j < 128; j++) {
            float4 bv = *(float4*)&Vs[j * 64 + tx * 4];
            float pv[8];
#pragma unroll
            for (int r = 0; r < 8; r++) pv[r] = Ss[(ty * 8 + r) * 128 + j];
#pragma unroll
            for (int r = 0; r < 8; r++) {
                o[r][0] += pv[r] * bv.x;
                o[r][1] += pv[r] * bv.y;
                o[r][2] += pv[r] * bv.z;
                o[r][3] += pv[r] * bv.w;
            }
        }
        __syncthreads();
    }

    // ---- epilogue: O / l ----
#pragma unroll
    for (int r = 0; r < 8; r++) {
        int i = ty * 8 + r;
        float inv = 1.f / s_l[i];
        int qi = qt * 128 + i;
        float4 v = make_float4(o[r][0] * inv, o[r][1] * inv,
                               o[r][2] * inv, o[r][3] * inv);
        *(float4*)(out + hb + (size_t)qi * DH + tx * 4) = v;
    }
}

// ============================================================================
// launch
// ============================================================================
extern "C" void kernel_launch(void* const* d_in, const int* in_sizes, int n_in,
                              void* d_out, int out_size)
{
    const float* x   = (const float*)d_in[0];   // [4,1024,1024]
    const float* Wq  = (const float*)d_in[1];   // [1024, 1024]
    const float* Wkv = (const float*)d_in[2];   // [1024, 2048]
    const float* pe  = (const float*)d_in[3];   // [1025, 64]
    float* out = (float*)d_out;                 // [4,16,1024,64]

    dim3 gproj(8, 32);      // 1024 cols / 128, 4096 rows / 128
    proj_kernel<<<gproj, 256>>>(x, Wq, 1024, 0, 0);      // -> g_Q
    proj_kernel<<<gproj, 256>>>(x, Wkv, 2048, 0, 1);     // -> g_K
    proj_kernel<<<gproj, 256>>>(x, Wkv, 2048, 1024, 2);  // -> g_V

    qp_kernel<<<dim3(9, 512), 256>>>(pe);                // qp = Q @ PE^T

    cudaFuncSetAttribute(attn_kernel,
                         cudaFuncAttributeMaxDynamicSharedMemorySize, SMEM_ATTN);
    attn_kernel<<<dim3(64, 8), 256, SMEM_ATTN>>>(out);
}

// round 4
// speedup vs baseline: 1.5829x; 1.5829x over previous
#include <cuda_runtime.h>
#include <cuda_bf16.h>
#include <math.h>
#include <stdint.h>

#define HEADS 16
#define DH 64
#define NB 4
#define NSEQ 1024
#define DIMIN 1024
#define BH (NB * HEADS)          // 64
#define MROWS (NB * NSEQ)        // 4096
#define NPROJ 3072
#define PE_PAD 1152
#define QP_LD 1056
#define ATT_SCALE 0.125f

// ---- scratch (device globals; referenced ONLY from device code) ----
__device__ float g_Q[(size_t)BH * NSEQ * DH];
__device__ float g_K[(size_t)BH * NSEQ * DH];
__device__ float g_V[(size_t)BH * NSEQ * DH];
__device__ float g_QP[(size_t)BH * NSEQ * QP_LD];               // 277 MB
__device__ __align__(16) __nv_bfloat16 g_xh[(size_t)MROWS * DIMIN];
__device__ __align__(16) __nv_bfloat16 g_xl[(size_t)MROWS * DIMIN];
__device__ __align__(16) __nv_bfloat16 g_wh[(size_t)NPROJ * DIMIN];  // W^T [n][k]
__device__ __align__(16) __nv_bfloat16 g_wl[(size_t)NPROJ * DIMIN];
__device__ __align__(16) __nv_bfloat16 g_qh[(size_t)BH * NSEQ * DH];
__device__ __align__(16) __nv_bfloat16 g_ql[(size_t)BH * NSEQ * DH];
__device__ __align__(16) __nv_bfloat16 g_peh[(size_t)PE_PAD * DH];
__device__ __align__(16) __nv_bfloat16 g_pel[(size_t)PE_PAD * DH];

// ============================================================================
// mma.sync helper (baseline PTX, works on plain sm_103 target)
// ============================================================================
__device__ __forceinline__ void mma16816(float* c, const uint32_t* a, const uint32_t* b) {
    asm volatile(
        "mma.sync.aligned.m16n8k16.row.col.f32.bf16.bf16.f32 "
        "{%0,%1,%2,%3}, {%4,%5,%6,%7}, {%8,%9}, {%0,%1,%2,%3};"
        : "+f"(c[0]), "+f"(c[1]), "+f"(c[2]), "+f"(c[3])
        : "r"(a[0]), "r"(a[1]), "r"(a[2]), "r"(a[3]), "r"(b[0]), "r"(b[1]));
}

// ============================================================================
// conversion kernels (fp32 -> bf16 hi/lo split) — globals referenced in-device
// ============================================================================
__global__ void conv_x(const float* __restrict__ in)
{
    int i = blockIdx.x * 256 + threadIdx.x;
    if (i < MROWS * DIMIN) {
        float v = in[i];
        __nv_bfloat16 h = __float2bfloat16(v);
        g_xh[i] = h;
        g_xl[i] = __float2bfloat16(v - __bfloat162float(h));
    }
}

// W transpose + split: g_wh/g_wl[n][k] = split(W[k][n]); n<1024 from Wq else Wkv
__global__ __launch_bounds__(256)
void conv_wT(const float* __restrict__ Wq, const float* __restrict__ Wkv)
{
    __shared__ float t[32][33];
    int nb = blockIdx.x * 32, kb = blockIdx.y * 32;
    int tx = threadIdx.x & 31, ty = threadIdx.x >> 5;
#pragma unroll
    for (int r = 0; r < 4; r++) {
        int k = kb + ty + r * 8, n = nb + tx;
        float v = (n < 1024) ? Wq[(size_t)k * 1024 + n]
                             : Wkv[(size_t)k * 2048 + (n - 1024)];
        t[ty + r * 8][tx] = v;
    }
    __syncthreads();
#pragma unroll
    for (int r = 0; r < 4; r++) {
        int n = nb + ty + r * 8, k = kb + tx;
        float v = t[tx][ty + r * 8];
        __nv_bfloat16 h = __float2bfloat16(v);
        g_wh[(size_t)n * 1024 + k] = h;
        g_wl[(size_t)n * 1024 + k] = __float2bfloat16(v - __bfloat162float(h));
    }
}

__global__ void conv_pe(const float* __restrict__ pe)
{
    int i = blockIdx.x * 256 + threadIdx.x;
    if (i >= PE_PAD * DH) return;
    int p = i >> 6;
    float v = (p < 2 * 512 + 1) ? pe[i] : 0.f;
    __nv_bfloat16 h = __float2bfloat16(v);
    g_peh[i] = h;
    g_pel[i] = __float2bfloat16(v - __bfloat162float(h));
}

// ============================================================================
// proj GEMM via mma.sync: C[4096,3072] = X[4096,1024] @ W[1024,3072]
// split-bf16 3 products. 128x128 CTA tile, 8 warps (2x4), K-chunk 32.
// ============================================================================
#define LDA 56
#define TILE_E (128 * LDA)

__global__ __launch_bounds__(256, 2)
void proj_mma()
{
    extern __shared__ __nv_bfloat16 sm[];
    __nv_bfloat16* Ah = sm;
    __nv_bfloat16* Al = sm + TILE_E;
    __nv_bfloat16* Bh = sm + 2 * TILE_E;
    __nv_bfloat16* Bl = sm + 3 * TILE_E;

    const int tid = threadIdx.x;
    const int wid = tid >> 5, lane = tid & 31;
    const int g = lane >> 2, tg = lane & 3;
    const int n0 = blockIdx.x * 128, m0 = blockIdx.y * 128;
    const int wm = (wid >> 2) * 64, wn = (wid & 3) * 32;

    float c[4][4][4];
#pragma unroll
    for (int mt = 0; mt < 4; mt++)
#pragma unroll
        for (int nt = 0; nt < 4; nt++)
#pragma unroll
            for (int e = 0; e < 4; e++) c[mt][nt][e] = 0.f;

    for (int kc = 0; kc < 32; kc++) {
        const int k0 = kc * 32;
#pragma unroll
        for (int p = 0; p < 2; p++) {
            int idx = tid + p * 256;
            int row = idx >> 2, unit = idx & 3;
            size_t gA = (size_t)(m0 + row) * DIMIN + k0 + unit * 8;
            size_t gB = (size_t)(n0 + row) * DIMIN + k0 + unit * 8;
            int so = row * LDA + unit * 8;
            *(uint4*)(Ah + so) = *(const uint4*)(g_xh + gA);
            *(uint4*)(Al + so) = *(const uint4*)(g_xl + gA);
            *(uint4*)(Bh + so) = *(const uint4*)(g_wh + gB);
            *(uint4*)(Bl + so) = *(const uint4*)(g_wl + gB);
        }
        __syncthreads();

#pragma unroll
        for (int ks = 0; ks < 2; ks++) {
            const int cb = ks * 16 + tg * 2;
            uint32_t bh[4][2], bl[4][2];
#pragma unroll
            for (int nt = 0; nt < 4; nt++) {
                int n = (wn + nt * 8 + g) * LDA + cb;
                bh[nt][0] = *(uint32_t*)(Bh + n);
                bh[nt][1] = *(uint32_t*)(Bh + n + 8);
                bl[nt][0] = *(uint32_t*)(Bl + n);
                bl[nt][1] = *(uint32_t*)(Bl + n + 8);
            }
#pragma unroll
            for (int mt = 0; mt < 4; mt++) {
                int r0 = (wm + mt * 16 + g) * LDA + cb;
                int r8 = r0 + 8 * LDA;
                uint32_t ah[4], al[4];
                ah[0] = *(uint32_t*)(Ah + r0);
                ah[1] = *(uint32_t*)(Ah + r8);
                ah[2] = *(uint32_t*)(Ah + r0 + 8);
                ah[3] = *(uint32_t*)(Ah + r8 + 8);
                al[0] = *(uint32_t*)(Al + r0);
                al[1] = *(uint32_t*)(Al + r8);
                al[2] = *(uint32_t*)(Al + r0 + 8);
                al[3] = *(uint32_t*)(Al + r8 + 8);
#pragma unroll
                for (int nt = 0; nt < 4; nt++) {
                    mma16816(c[mt][nt], ah, bh[nt]);
                    mma16816(c[mt][nt], ah, bl[nt]);
                    mma16816(c[mt][nt], al, bh[nt]);
                }
            }
        }
        __syncthreads();
    }

    // epilogue: scatter to g_Q/g_K/g_V (+ bf16 split of Q)
    const int tgt = n0 >> 10;                // 0:Q 1:K 2:V
    float* outp = (tgt == 0) ? g_Q : (tgt == 1) ? g_K : g_V;
    const int nc0 = n0 & 1023;
#pragma unroll
    for (int mt = 0; mt < 4; mt++) {
#pragma unroll
        for (int half = 0; half < 2; half++) {
            int gi = m0 + wm + mt * 16 + g + half * 8;
            int b = gi >> 10, ii = gi & 1023;
            size_t rowbase = ((size_t)(b * HEADS) * NSEQ + ii) * DH;
#pragma unroll
            for (int nt = 0; nt < 4; nt++) {
                int gc = nc0 + wn + nt * 8 + tg * 2;
                int h = gc >> 6, d = gc & 63;
                size_t oidx = rowbase + (size_t)h * NSEQ * DH + d;
                float v0 = c[mt][nt][half * 2 + 0];
                float v1 = c[mt][nt][half * 2 + 1];
                *(float2*)(outp + oidx) = make_float2(v0, v1);
                if (tgt == 0) {
                    __nv_bfloat16 h0 = __float2bfloat16(v0);
                    __nv_bfloat16 h1 = __float2bfloat16(v1);
                    *(__nv_bfloat162*)(g_qh + oidx) = __nv_bfloat162(h0, h1);
                    *(__nv_bfloat162*)(g_ql + oidx) = __nv_bfloat162(
                        __float2bfloat16(v0 - __bfloat162float(h0)),
                        __float2bfloat16(v1 - __bfloat162float(h1)));
                }
            }
        }
    }
}

// ============================================================================
// qp GEMM via mma.sync: QP[65536,1025] = Qs[65536,64] @ PE[1152,64]^T
// ============================================================================
#define LDA2 72
#define TILE_E2 (128 * LDA2)

__global__ __launch_bounds__(256, 2)
void qp_mma()
{
    extern __shared__ __nv_bfloat16 sm2[];
    __nv_bfloat16* Ah = sm2;
    __nv_bfloat16* Al = sm2 + TILE_E2;
    __nv_bfloat16* Bh = sm2 + 2 * TILE_E2;
    __nv_bfloat16* Bl = sm2 + 3 * TILE_E2;

    const int tid = threadIdx.x;
    const int wid = tid >> 5, lane = tid & 31;
    const int g = lane >> 2, tg = lane & 3;
    const int p0 = blockIdx.x * 128, m0 = blockIdx.y * 128;
    const int wm = (wid >> 2) * 64, wn = (wid & 3) * 32;

    float c[4][4][4];
#pragma unroll
    for (int mt = 0; mt < 4; mt++)
#pragma unroll
        for (int nt = 0; nt < 4; nt++)
#pragma unroll
            for (int e = 0; e < 4; e++) c[mt][nt][e] = 0.f;

#pragma unroll
    for (int p = 0; p < 4; p++) {
        int idx = tid + p * 256;
        int row = idx >> 3, unit = idx & 7;
        size_t gA = (size_t)(m0 + row) * DH + unit * 8;
        size_t gB = (size_t)(p0 + row) * DH + unit * 8;
        int so = row * LDA2 + unit * 8;
        *(uint4*)(Ah + so) = *(const uint4*)(g_qh + gA);
        *(uint4*)(Al + so) = *(const uint4*)(g_ql + gA);
        *(uint4*)(Bh + so) = *(const uint4*)(g_peh + gB);
        *(uint4*)(Bl + so) = *(const uint4*)(g_pel + gB);
    }
    __syncthreads();

#pragma unroll
    for (int ks = 0; ks < 4; ks++) {
        const int cb = ks * 16 + tg * 2;
        uint32_t bh[4][2], bl[4][2];
#pragma unroll
        for (int nt = 0; nt < 4; nt++) {
            int n = (wn + nt * 8 + g) * LDA2 + cb;
            bh[nt][0] = *(uint32_t*)(Bh + n);
            bh[nt][1] = *(uint32_t*)(Bh + n + 8);
            bl[nt][0] = *(uint32_t*)(Bl + n);
            bl[nt][1] = *(uint32_t*)(Bl + n + 8);
        }
#pragma unroll
        for (int mt = 0; mt < 4; mt++) {
            int r0 = (wm + mt * 16 + g) * LDA2 + cb;
            int r8 = r0 + 8 * LDA2;
            uint32_t ah[4], al[4];
            ah[0] = *(uint32_t*)(Ah + r0);
            ah[1] = *(uint32_t*)(Ah + r8);
            ah[2] = *(uint32_t*)(Ah + r0 + 8);
            ah[3] = *(uint32_t*)(Ah + r8 + 8);
            al[0] = *(uint32_t*)(Al + r0);
            al[1] = *(uint32_t*)(Al + r8);
            al[2] = *(uint32_t*)(Al + r0 + 8);
            al[3] = *(uint32_t*)(Al + r8 + 8);
#pragma unroll
            for (int nt = 0; nt < 4; nt++) {
                mma16816(c[mt][nt], ah, bh[nt]);
                mma16816(c[mt][nt], ah, bl[nt]);
                mma16816(c[mt][nt], al, bh[nt]);
            }
        }
    }

    // epilogue
#pragma unroll
    for (int mt = 0; mt < 4; mt++) {
#pragma unroll
        for (int half = 0; half < 2; half++) {
            int gi = m0 + wm + mt * 16 + g + half * 8;
            size_t rb = (size_t)gi * QP_LD;
#pragma unroll
            for (int nt = 0; nt < 4; nt++) {
                int pp = p0 + wn + nt * 8 + tg * 2;
                if (pp + 1 < 1025) {
                    *(float2*)(g_QP + rb + pp) =
                        make_float2(c[mt][nt][half * 2], c[mt][nt][half * 2 + 1]);
                } else if (pp < 1025) {
                    g_QP[rb + pp] = c[mt][nt][half * 2];
                }
            }
        }
    }
}

// ============================================================================
// Fused flash attention with qp-gather bias (unchanged)
// ============================================================================
#define LD132 132
#define SMEM_ATTN ((2 * 64 * LD132 + 128 * 64 + 128 * 128 + 3 * 128) * 4)

__global__ __launch_bounds__(256, 1)
void attn_kernel(float* __restrict__ out)
{
    extern __shared__ float smf[];
    float* Qst = smf;
    float* Kst = Qst + 64 * LD132;
    float* Vs  = Kst + 64 * LD132;
    float* Ss  = Vs + 128 * 64;
    float* s_m = Ss + 128 * 128;
    float* s_l = s_m + 128;
    float* s_r = s_l + 128;

    const int tid = threadIdx.x;
    const int bh = blockIdx.x;
    const int qt = blockIdx.y;
    const size_t hb = (size_t)bh * NSEQ * DH;

#pragma unroll
    for (int rep = 0; rep < 8; rep++) {
        int idx = tid + rep * 256;
        int l = idx >> 4, d4 = (idx & 15) * 4;
        float4 v = *(const float4*)(g_Q + hb + (size_t)(qt * 128 + l) * DH + d4);
        Qst[(d4 + 0) * LD132 + l] = v.x;
        Qst[(d4 + 1) * LD132 + l] = v.y;
        Qst[(d4 + 2) * LD132 + l] = v.z;
        Qst[(d4 + 3) * LD132 + l] = v.w;
    }
    if (tid < 128) { s_m[tid] = -INFINITY; s_l[tid] = 0.f; }

    const int ty = tid >> 4, tx = tid & 15;
    float o[8][4];
#pragma unroll
    for (int r = 0; r < 8; r++)
#pragma unroll
        for (int c = 0; c < 4; c++) o[r][c] = 0.f;

    __syncthreads();

    for (int kt = 0; kt < 8; kt++) {
#pragma unroll
        for (int rep = 0; rep < 8; rep++) {
            int idx = tid + rep * 256;
            int l = idx >> 4, d4 = (idx & 15) * 4;
            size_t goff = hb + (size_t)(kt * 128 + l) * DH + d4;
            float4 kv = *(const float4*)(g_K + goff);
            Kst[(d4 + 0) * LD132 + l] = kv.x;
            Kst[(d4 + 1) * LD132 + l] = kv.y;
            Kst[(d4 + 2) * LD132 + l] = kv.z;
            Kst[(d4 + 3) * LD132 + l] = kv.w;
            float4 vv = *(const float4*)(g_V + goff);
            *(float4*)&Vs[l * 64 + d4] = vv;
        }
        __syncthreads();

        float c[8][8];
#pragma unroll
        for (int r = 0; r < 8; r++)
#pragma unroll
            for (int s = 0; s < 8; s++) c[r][s] = 0.f;

#pragma unroll 8
        for (int kk = 0; kk < 64; kk++) {
            float4 a0 = *(float4*)&Qst[kk * LD132 + ty * 8];
            float4 a1 = *(float4*)&Qst[kk * LD132 + ty * 8 + 4];
            float4 b0 = *(float4*)&Kst[kk * LD132 + tx * 8];
            float4 b1 = *(float4*)&Kst[kk * LD132 + tx * 8 + 4];
            float a[8] = {a0.x, a0.y, a0.z, a0.w, a1.x, a1.y, a1.z, a1.w};
            float b[8] = {b0.x, b0.y, b0.z, b0.w, b1.x, b1.y, b1.z, b1.w};
#pragma unroll
            for (int r = 0; r < 8; r++)
#pragma unroll
                for (int s = 0; s < 8; s++) c[r][s] += a[r] * b[s];
        }

#pragma unroll
        for (int r = 0; r < 8; r++) {
            int qi = qt * 128 + ty * 8 + r;
            const float* qpr = g_QP + ((size_t)bh * NSEQ + qi) * QP_LD;
#pragma unroll
            for (int s = 0; s < 8; s++) {
                int j = kt * 128 + tx * 8 + s;
                int dlt = qi - j;
                dlt = dlt > 512 ? 512 : (dlt < -512 ? -512 : dlt);
                float val = (c[r][s] + qpr[dlt + 512]) * ATT_SCALE;
                Ss[(ty * 8 + r) * 128 + tx * 8 + s] = val;
            }
        }
        __syncthreads();

        if (tid < 128) {
            const int i = tid;
            float mold = s_m[i];
            float mnew = mold;
#pragma unroll 8
            for (int jj = 0; jj < 128; jj++) {
                float v = Ss[i * 128 + ((jj + i) & 127)];
                mnew = fmaxf(mnew, v);
            }
            float rsc = __expf(mold - mnew);
            float lsum = 0.f;
#pragma unroll 8
            for (int jj = 0; jj < 128; jj++) {
                int j = (jj + i) & 127;
                float p = __expf(Ss[i * 128 + j] - mnew);
                Ss[i * 128 + j] = p;
                lsum += p;
            }
            s_l[i] = s_l[i] * rsc + lsum;
            s_m[i] = mnew;
            s_r[i] = rsc;
        }
        __syncthreads();

#pragma unroll
        for (int r = 0; r < 8; r++) {
            float rsc = s_r[ty * 8 + r];
#pragma unroll
            for (int cc = 0; cc < 4; cc++) o[r][cc] *= rsc;
        }
#pragma unroll 8
        for (int j = 0; j < 128; j++) {
            float4 bv = *(float4*)&Vs[j * 64 + tx * 4];
            float pv[8];
#pragma unroll
            for (int r = 0; r < 8; r++) pv[r] = Ss[(ty * 8 + r) * 128 + j];
#pragma unroll
            for (int r = 0; r < 8; r++) {
                o[r][0] += pv[r] * bv.x;
                o[r][1] += pv[r] * bv.y;
                o[r][2] += pv[r] * bv.z;
                o[r][3] += pv[r] * bv.w;
            }
        }
        __syncthreads();
    }

#pragma unroll
    for (int r = 0; r < 8; r++) {
        int i = ty * 8 + r;
        float inv = 1.f / s_l[i];
        int qi = qt * 128 + i;
        float4 v = make_float4(o[r][0] * inv, o[r][1] * inv,
                               o[r][2] * inv, o[r][3] * inv);
        *(float4*)(out + hb + (size_t)qi * DH + tx * 4) = v;
    }
}

// ============================================================================
// launch
// ============================================================================
extern "C" void kernel_launch(void* const* d_in, const int* in_sizes, int n_in,
                              void* d_out, int out_size)
{
    const float* x   = (const float*)d_in[0];   // [4,1024,1024]
    const float* Wq  = (const float*)d_in[1];   // [1024, 1024]
    const float* Wkv = (const float*)d_in[2];   // [1024, 2048]
    const float* pe  = (const float*)d_in[3];   // [1025, 64]
    float* out = (float*)d_out;                 // [4,16,1024,64]

    conv_x<<<(MROWS * DIMIN + 255) / 256, 256>>>(x);
    conv_wT<<<dim3(NPROJ / 32, DIMIN / 32), 256>>>(Wq, Wkv);
    conv_pe<<<(PE_PAD * DH + 255) / 256, 256>>>(pe);

    const int smem_proj = 4 * TILE_E * (int)sizeof(__nv_bfloat16);   // 57344
    cudaFuncSetAttribute(proj_mma, cudaFuncAttributeMaxDynamicSharedMemorySize, smem_proj);
    proj_mma<<<dim3(NPROJ / 128, MROWS / 128), 256, smem_proj>>>();

    const int smem_qp = 4 * TILE_E2 * (int)sizeof(__nv_bfloat16);    // 73728
    cudaFuncSetAttribute(qp_mma, cudaFuncAttributeMaxDynamicSharedMemorySize, smem_qp);
    qp_mma<<<dim3(9, 512), 256, smem_qp>>>();

    cudaFuncSetAttribute(attn_kernel, cudaFuncAttributeMaxDynamicSharedMemorySize, SMEM_ATTN);
    attn_kernel<<<dim3(64, 8), 256, SMEM_ATTN>>>(out);
}

// round 5
// speedup vs baseline: 2.2839x; 1.4429x over previous
#include <cuda_runtime.h>
#include <cuda_bf16.h>
#include <math.h>
#include <stdint.h>

#define HEADS 16
#define DH 64
#define NB 4
#define NSEQ 1024
#define DIMIN 1024
#define BH (NB * HEADS)          // 64
#define MROWS (NB * NSEQ)        // 4096
#define NPROJ 3072
#define PE_PAD 1152
#define QP_LD 1056
#define ATT_SCALE 0.125f

// ---- scratch (device globals; referenced ONLY from device code) ----
__device__ float g_QP[(size_t)BH * NSEQ * QP_LD];               // 277 MB
__device__ __align__(16) __nv_bfloat16 g_xh[(size_t)MROWS * DIMIN];
__device__ __align__(16) __nv_bfloat16 g_xl[(size_t)MROWS * DIMIN];
__device__ __align__(16) __nv_bfloat16 g_wh[(size_t)NPROJ * DIMIN];  // W^T [n][k]
__device__ __align__(16) __nv_bfloat16 g_wl[(size_t)NPROJ * DIMIN];
__device__ __align__(16) __nv_bfloat16 g_qh[(size_t)BH * NSEQ * DH]; // [bh][n][d]
__device__ __align__(16) __nv_bfloat16 g_ql[(size_t)BH * NSEQ * DH];
__device__ __align__(16) __nv_bfloat16 g_kh[(size_t)BH * NSEQ * DH]; // [bh][n][d]
__device__ __align__(16) __nv_bfloat16 g_kl[(size_t)BH * NSEQ * DH];
__device__ __align__(16) __nv_bfloat16 g_vth[(size_t)BH * DH * NSEQ]; // [bh][d][n]
__device__ __align__(16) __nv_bfloat16 g_vtl[(size_t)BH * DH * NSEQ];
__device__ __align__(16) __nv_bfloat16 g_peh[(size_t)PE_PAD * DH];
__device__ __align__(16) __nv_bfloat16 g_pel[(size_t)PE_PAD * DH];

// ============================================================================
// mma.sync helper (baseline PTX)
// ============================================================================
__device__ __forceinline__ void mma16816(float* c, const uint32_t* a, const uint32_t* b) {
    asm volatile(
        "mma.sync.aligned.m16n8k16.row.col.f32.bf16.bf16.f32 "
        "{%0,%1,%2,%3}, {%4,%5,%6,%7}, {%8,%9}, {%0,%1,%2,%3};"
        : "+f"(c[0]), "+f"(c[1]), "+f"(c[2]), "+f"(c[3])
        : "r"(a[0]), "r"(a[1]), "r"(a[2]), "r"(a[3]), "r"(b[0]), "r"(b[1]));
}

__device__ __forceinline__ uint32_t packsplit(float x, float y, uint32_t& lo) {
    __nv_bfloat16 hx = __float2bfloat16(x), hy = __float2bfloat16(y);
    __nv_bfloat162 H(hx, hy);
    __nv_bfloat162 L(__float2bfloat16(x - __bfloat162float(hx)),
                     __float2bfloat16(y - __bfloat162float(hy)));
    lo = *(uint32_t*)&L;
    return *(uint32_t*)&H;
}

// ============================================================================
// conversion kernels
// ============================================================================
__global__ void conv_x(const float* __restrict__ in)
{
    int i = blockIdx.x * 256 + threadIdx.x;
    if (i < MROWS * DIMIN) {
        float v = in[i];
        __nv_bfloat16 h = __float2bfloat16(v);
        g_xh[i] = h;
        g_xl[i] = __float2bfloat16(v - __bfloat162float(h));
    }
}

__global__ __launch_bounds__(256)
void conv_wT(const float* __restrict__ Wq, const float* __restrict__ Wkv)
{
    __shared__ float t[32][33];
    int nb = blockIdx.x * 32, kb = blockIdx.y * 32;
    int tx = threadIdx.x & 31, ty = threadIdx.x >> 5;
#pragma unroll
    for (int r = 0; r < 4; r++) {
        int k = kb + ty + r * 8, n = nb + tx;
        float v = (n < 1024) ? Wq[(size_t)k * 1024 + n]
                             : Wkv[(size_t)k * 2048 + (n - 1024)];
        t[ty + r * 8][tx] = v;
    }
    __syncthreads();
#pragma unroll
    for (int r = 0; r < 4; r++) {
        int n = nb + ty + r * 8, k = kb + tx;
        float v = t[tx][ty + r * 8];
        __nv_bfloat16 h = __float2bfloat16(v);
        g_wh[(size_t)n * 1024 + k] = h;
        g_wl[(size_t)n * 1024 + k] = __float2bfloat16(v - __bfloat162float(h));
    }
}

__global__ void conv_pe(const float* __restrict__ pe)
{
    int i = blockIdx.x * 256 + threadIdx.x;
    if (i >= PE_PAD * DH) return;
    int p = i >> 6;
    float v = (p < 2 * 512 + 1) ? pe[i] : 0.f;
    __nv_bfloat16 h = __float2bfloat16(v);
    g_peh[i] = h;
    g_pel[i] = __float2bfloat16(v - __bfloat162float(h));
}

// ============================================================================
// proj GEMM: C[4096,3072] = X @ W; epilogue emits bf16 hi/lo Q,K and V^T
// ============================================================================
#define LDA 56
#define TILE_E (128 * LDA)

__global__ __launch_bounds__(256, 2)
void proj_mma()
{
    extern __shared__ __nv_bfloat16 sm[];
    __nv_bfloat16* Ah = sm;
    __nv_bfloat16* Al = sm + TILE_E;
    __nv_bfloat16* Bh = sm + 2 * TILE_E;
    __nv_bfloat16* Bl = sm + 3 * TILE_E;

    const int tid = threadIdx.x;
    const int wid = tid >> 5, lane = tid & 31;
    const int g = lane >> 2, tg = lane & 3;
    const int n0 = blockIdx.x * 128, m0 = blockIdx.y * 128;
    const int wm = (wid >> 2) * 64, wn = (wid & 3) * 32;

    float c[4][4][4];
#pragma unroll
    for (int mt = 0; mt < 4; mt++)
#pragma unroll
        for (int nt = 0; nt < 4; nt++)
#pragma unroll
            for (int e = 0; e < 4; e++) c[mt][nt][e] = 0.f;

    for (int kc = 0; kc < 32; kc++) {
        const int k0 = kc * 32;
#pragma unroll
        for (int p = 0; p < 2; p++) {
            int idx = tid + p * 256;
            int row = idx >> 2, unit = idx & 3;
            size_t gA = (size_t)(m0 + row) * DIMIN + k0 + unit * 8;
            size_t gB = (size_t)(n0 + row) * DIMIN + k0 + unit * 8;
            int so = row * LDA + unit * 8;
            *(uint4*)(Ah + so) = *(const uint4*)(g_xh + gA);
            *(uint4*)(Al + so) = *(const uint4*)(g_xl + gA);
            *(uint4*)(Bh + so) = *(const uint4*)(g_wh + gB);
            *(uint4*)(Bl + so) = *(const uint4*)(g_wl + gB);
        }
        __syncthreads();

#pragma unroll
        for (int ks = 0; ks < 2; ks++) {
            const int cb = ks * 16 + tg * 2;
            uint32_t bh[4][2], bl[4][2];
#pragma unroll
            for (int nt = 0; nt < 4; nt++) {
                int n = (wn + nt * 8 + g) * LDA + cb;
                bh[nt][0] = *(uint32_t*)(Bh + n);
                bh[nt][1] = *(uint32_t*)(Bh + n + 8);
                bl[nt][0] = *(uint32_t*)(Bl + n);
                bl[nt][1] = *(uint32_t*)(Bl + n + 8);
            }
#pragma unroll
            for (int mt = 0; mt < 4; mt++) {
                int r0 = (wm + mt * 16 + g) * LDA + cb;
                int r8 = r0 + 8 * LDA;
                uint32_t ah[4], al[4];
                ah[0] = *(uint32_t*)(Ah + r0);
                ah[1] = *(uint32_t*)(Ah + r8);
                ah[2] = *(uint32_t*)(Ah + r0 + 8);
                ah[3] = *(uint32_t*)(Ah + r8 + 8);
                al[0] = *(uint32_t*)(Al + r0);
                al[1] = *(uint32_t*)(Al + r8);
                al[2] = *(uint32_t*)(Al + r0 + 8);
                al[3] = *(uint32_t*)(Al + r8 + 8);
#pragma unroll
                for (int nt = 0; nt < 4; nt++) {
                    mma16816(c[mt][nt], ah, bh[nt]);
                    mma16816(c[mt][nt], ah, bl[nt]);
                    mma16816(c[mt][nt], al, bh[nt]);
                }
            }
        }
        __syncthreads();
    }

    // epilogue: split to bf16 hi/lo; Q,K -> [bh][n][d]; V -> transposed [bh][d][n]
    const int tgt = n0 >> 10;                // 0:Q 1:K 2:V
    const int nc0 = n0 & 1023;
#pragma unroll
    for (int mt = 0; mt < 4; mt++) {
#pragma unroll
        for (int half = 0; half < 2; half++) {
            int gi = m0 + wm + mt * 16 + g + half * 8;
            int b = gi >> 10, ii = gi & 1023;
#pragma unroll
            for (int nt = 0; nt < 4; nt++) {
                int gc = nc0 + wn + nt * 8 + tg * 2;
                int h = gc >> 6, d = gc & 63;
                int bh_i = b * HEADS + h;
                float v0 = c[mt][nt][half * 2 + 0];
                float v1 = c[mt][nt][half * 2 + 1];
                uint32_t lo;
                uint32_t hi = packsplit(v0, v1, lo);
                if (tgt == 0) {
                    size_t oidx = ((size_t)bh_i * NSEQ + ii) * DH + d;
                    *(uint32_t*)(g_qh + oidx) = hi;
                    *(uint32_t*)(g_ql + oidx) = lo;
                } else if (tgt == 1) {
                    size_t oidx = ((size_t)bh_i * NSEQ + ii) * DH + d;
                    *(uint32_t*)(g_kh + oidx) = hi;
                    *(uint32_t*)(g_kl + oidx) = lo;
                } else {
                    __nv_bfloat162 H = *(__nv_bfloat162*)&hi;
                    __nv_bfloat162 L = *(__nv_bfloat162*)&lo;
                    size_t t0 = ((size_t)bh_i * DH + d) * NSEQ + ii;
                    size_t t1 = ((size_t)bh_i * DH + d + 1) * NSEQ + ii;
                    g_vth[t0] = H.x; g_vth[t1] = H.y;
                    g_vtl[t0] = L.x; g_vtl[t1] = L.y;
                }
            }
        }
    }
}

// ============================================================================
// qp GEMM: QP[65536,1025] = Qs[65536,64] @ PE[1152,64]^T
// ============================================================================
#define LDA2 72
#define TILE_E2 (128 * LDA2)

__global__ __launch_bounds__(256, 2)
void qp_mma()
{
    extern __shared__ __nv_bfloat16 sm2[];
    __nv_bfloat16* Ah = sm2;
    __nv_bfloat16* Al = sm2 + TILE_E2;
    __nv_bfloat16* Bh = sm2 + 2 * TILE_E2;
    __nv_bfloat16* Bl = sm2 + 3 * TILE_E2;

    const int tid = threadIdx.x;
    const int wid = tid >> 5, lane = tid & 31;
    const int g = lane >> 2, tg = lane & 3;
    const int p0 = blockIdx.x * 128, m0 = blockIdx.y * 128;
    const int wm = (wid >> 2) * 64, wn = (wid & 3) * 32;

    float c[4][4][4];
#pragma unroll
    for (int mt = 0; mt < 4; mt++)
#pragma unroll
        for (int nt = 0; nt < 4; nt++)
#pragma unroll
            for (int e = 0; e < 4; e++) c[mt][nt][e] = 0.f;

#pragma unroll
    for (int p = 0; p < 4; p++) {
        int idx = tid + p * 256;
        int row = idx >> 3, unit = idx & 7;
        size_t gA = (size_t)(m0 + row) * DH + unit * 8;
        size_t gB = (size_t)(p0 + row) * DH + unit * 8;
        int so = row * LDA2 + unit * 8;
        *(uint4*)(Ah + so) = *(const uint4*)(g_qh + gA);
        *(uint4*)(Al + so) = *(const uint4*)(g_ql + gA);
        *(uint4*)(Bh + so) = *(const uint4*)(g_peh + gB);
        *(uint4*)(Bl + so) = *(const uint4*)(g_pel + gB);
    }
    __syncthreads();

#pragma unroll
    for (int ks = 0; ks < 4; ks++) {
        const int cb = ks * 16 + tg * 2;
        uint32_t bh[4][2], bl[4][2];
#pragma unroll
        for (int nt = 0; nt < 4; nt++) {
            int n = (wn + nt * 8 + g) * LDA2 + cb;
            bh[nt][0] = *(uint32_t*)(Bh + n);
            bh[nt][1] = *(uint32_t*)(Bh + n + 8);
            bl[nt][0] = *(uint32_t*)(Bl + n);
            bl[nt][1] = *(uint32_t*)(Bl + n + 8);
        }
#pragma unroll
        for (int mt = 0; mt < 4; mt++) {
            int r0 = (wm + mt * 16 + g) * LDA2 + cb;
            int r8 = r0 + 8 * LDA2;
            uint32_t ah[4], al[4];
            ah[0] = *(uint32_t*)(Ah + r0);
            ah[1] = *(uint32_t*)(Ah + r8);
            ah[2] = *(uint32_t*)(Ah + r0 + 8);
            ah[3] = *(uint32_t*)(Ah + r8 + 8);
            al[0] = *(uint32_t*)(Al + r0);
            al[1] = *(uint32_t*)(Al + r8);
            al[2] = *(uint32_t*)(Al + r0 + 8);
            al[3] = *(uint32_t*)(Al + r8 + 8);
#pragma unroll
            for (int nt = 0; nt < 4; nt++) {
                mma16816(c[mt][nt], ah, bh[nt]);
                mma16816(c[mt][nt], ah, bl[nt]);
                mma16816(c[mt][nt], al, bh[nt]);
            }
        }
    }

#pragma unroll
    for (int mt = 0; mt < 4; mt++) {
#pragma unroll
        for (int half = 0; half < 2; half++) {
            int gi = m0 + wm + mt * 16 + g + half * 8;
            size_t rb = (size_t)gi * QP_LD;
#pragma unroll
            for (int nt = 0; nt < 4; nt++) {
                int pp = p0 + wn + nt * 8 + tg * 2;
                if (pp + 1 < 1025) {
                    *(float2*)(g_QP + rb + pp) =
                        make_float2(c[mt][nt][half * 2], c[mt][nt][half * 2 + 1]);
                } else if (pp < 1025) {
                    g_QP[rb + pp] = c[mt][nt][half * 2];
                }
            }
        }
    }
}

// ============================================================================
// Tensorized flash attention: mma.sync S + register softmax + mma.sync PV
// Block: 256 thr (8 warps), q-tile 128 (16 rows/warp), key tiles 128.
// ============================================================================
#define LDK 72     // bf16 stride for K/Q tiles [row][d]
#define LDV 136    // bf16 stride for V^T tiles [d][key]
#define LDQP 133   // fp32 stride for qp tile (conflict-free: 5*dg != 2*dtg)
#define SM_KH 0
#define SM_KL 18432
#define SM_VH 36864
#define SM_VL 54272
#define SM_QP 71680
#define SMEM_ATTN2 (SM_QP + 128 * LDQP * 4)   // 139776

__global__ __launch_bounds__(256, 1)
void attn_mma(float* __restrict__ out)
{
    extern __shared__ char sma[];
    __nv_bfloat16* Kh  = (__nv_bfloat16*)(sma + SM_KH);
    __nv_bfloat16* Kl  = (__nv_bfloat16*)(sma + SM_KL);
    __nv_bfloat16* Vth = (__nv_bfloat16*)(sma + SM_VH);
    __nv_bfloat16* Vtl = (__nv_bfloat16*)(sma + SM_VL);
    float* QPs = (float*)(sma + SM_QP);

    const int tid = threadIdx.x;
    const int wid = tid >> 5, lane = tid & 31;
    const int g = lane >> 2, tg = lane & 3;
    const int bh = blockIdx.x;
    const int qt = blockIdx.y;
    const size_t base = (size_t)bh * NSEQ * DH;
    const int wm = wid * 16;

    // ---- stage Q tile (hi/lo) into QPs area, fragment-load, then free ----
    {
        __nv_bfloat16* Qh = (__nv_bfloat16*)(sma + SM_QP);
        __nv_bfloat16* Ql = Qh + 128 * LDK;
#pragma unroll
        for (int p = 0; p < 4; p++) {
            int idx = tid + p * 256;
            int row = idx >> 3, dc = (idx & 7) * 8;
            size_t ga = base + (size_t)(qt * 128 + row) * DH + dc;
            *(uint4*)(Qh + row * LDK + dc) = *(const uint4*)(g_qh + ga);
            *(uint4*)(Ql + row * LDK + dc) = *(const uint4*)(g_ql + ga);
        }
        __syncthreads();
    }
    uint32_t qah[4][4], qal[4][4];
    {
        __nv_bfloat16* Qh = (__nv_bfloat16*)(sma + SM_QP);
        __nv_bfloat16* Ql = Qh + 128 * LDK;
#pragma unroll
        for (int kk = 0; kk < 4; kk++) {
            int r0 = (wm + g) * LDK + kk * 16 + tg * 2;
            int r8 = r0 + 8 * LDK;
            qah[kk][0] = *(uint32_t*)(Qh + r0);
            qah[kk][1] = *(uint32_t*)(Qh + r8);
            qah[kk][2] = *(uint32_t*)(Qh + r0 + 8);
            qah[kk][3] = *(uint32_t*)(Qh + r8 + 8);
            qal[kk][0] = *(uint32_t*)(Ql + r0);
            qal[kk][1] = *(uint32_t*)(Ql + r8);
            qal[kk][2] = *(uint32_t*)(Ql + r0 + 8);
            qal[kk][3] = *(uint32_t*)(Ql + r8 + 8);
        }
        __syncthreads();
    }

    const int qi0 = qt * 128 + wm + g;
    const int qi1 = qi0 + 8;
    const float* qpr0 = g_QP + ((size_t)bh * NSEQ + qi0) * QP_LD + 512;
    const float* qpr1 = g_QP + ((size_t)bh * NSEQ + qi1) * QP_LD + 512;
    (void)qpr0; (void)qpr1;

    float o[8][4];
#pragma unroll
    for (int nt = 0; nt < 8; nt++)
#pragma unroll
        for (int e = 0; e < 4; e++) o[nt][e] = 0.f;
    float m0r = -INFINITY, m1r = -INFINITY, l0r = 0.f, l1r = 0.f;

    for (int kt = 0; kt < 8; kt++) {
        // ---- stage K (hi/lo), V^T (hi/lo), qp patch ----
#pragma unroll
        for (int p = 0; p < 4; p++) {
            int idx = tid + p * 256;
            int row = idx >> 3, dc = (idx & 7) * 8;
            size_t ga = base + (size_t)(kt * 128 + row) * DH + dc;
            *(uint4*)(Kh + row * LDK + dc) = *(const uint4*)(g_kh + ga);
            *(uint4*)(Kl + row * LDK + dc) = *(const uint4*)(g_kl + ga);
        }
#pragma unroll
        for (int p = 0; p < 4; p++) {
            int idx = tid + p * 256;
            int dr = idx >> 4, kc = (idx & 15) * 8;
            size_t ga = ((size_t)bh * DH + dr) * NSEQ + kt * 128 + kc;
            *(uint4*)(Vth + dr * LDV + kc) = *(const uint4*)(g_vth + ga);
            *(uint4*)(Vtl + dr * LDV + kc) = *(const uint4*)(g_vtl + ga);
        }
#pragma unroll 8
        for (int p = 0; p < 64; p++) {
            int idx = tid + p * 256;
            int row = idx >> 7, col = idx & 127;
            int qi = qt * 128 + row;
            int dlt = qi - (kt * 128 + col);
            dlt = dlt > 512 ? 512 : (dlt < -512 ? -512 : dlt);
            QPs[row * LDQP + col] = g_QP[((size_t)bh * NSEQ + qi) * QP_LD + dlt + 512];
        }
        __syncthreads();

        // ---- S = Q K^T (split-bf16, 3 products) ----
        float c[16][4];
#pragma unroll
        for (int nt = 0; nt < 16; nt++)
#pragma unroll
            for (int e = 0; e < 4; e++) c[nt][e] = 0.f;
#pragma unroll
        for (int kk = 0; kk < 4; kk++) {
#pragma unroll
            for (int nt = 0; nt < 16; nt++) {
                int n = (nt * 8 + g) * LDK + kk * 16 + tg * 2;
                uint32_t bfh[2], bfl[2];
                bfh[0] = *(uint32_t*)(Kh + n);
                bfh[1] = *(uint32_t*)(Kh + n + 8);
                bfl[0] = *(uint32_t*)(Kl + n);
                bfl[1] = *(uint32_t*)(Kl + n + 8);
                mma16816(c[nt], qah[kk], bfh);
                mma16816(c[nt], qal[kk], bfh);
                mma16816(c[nt], qah[kk], bfl);
            }
        }

        // ---- bias + scale (in place), track row max ----
        float mx0 = m0r, mx1 = m1r;
#pragma unroll
        for (int nt = 0; nt < 16; nt++) {
            int colb = nt * 8 + tg * 2;
            int ro = (wm + g) * LDQP + colb;
            float b00 = QPs[ro], b01 = QPs[ro + 1];
            float b10 = QPs[ro + 8 * LDQP], b11 = QPs[ro + 8 * LDQP + 1];
            c[nt][0] = (c[nt][0] + b00) * ATT_SCALE;
            c[nt][1] = (c[nt][1] + b01) * ATT_SCALE;
            c[nt][2] = (c[nt][2] + b10) * ATT_SCALE;
            c[nt][3] = (c[nt][3] + b11) * ATT_SCALE;
            mx0 = fmaxf(mx0, fmaxf(c[nt][0], c[nt][1]));
            mx1 = fmaxf(mx1, fmaxf(c[nt][2], c[nt][3]));
        }
        mx0 = fmaxf(mx0, __shfl_xor_sync(0xffffffff, mx0, 1));
        mx0 = fmaxf(mx0, __shfl_xor_sync(0xffffffff, mx0, 2));
        mx1 = fmaxf(mx1, __shfl_xor_sync(0xffffffff, mx1, 1));
        mx1 = fmaxf(mx1, __shfl_xor_sync(0xffffffff, mx1, 2));

        float rsc0 = __expf(m0r - mx0);
        float rsc1 = __expf(m1r - mx1);
        m0r = mx0; m1r = mx1;

        float sum0 = 0.f, sum1 = 0.f;
#pragma unroll
        for (int nt = 0; nt < 16; nt++) {
            c[nt][0] = __expf(c[nt][0] - mx0);
            c[nt][1] = __expf(c[nt][1] - mx0);
            c[nt][2] = __expf(c[nt][2] - mx1);
            c[nt][3] = __expf(c[nt][3] - mx1);
            sum0 += c[nt][0] + c[nt][1];
            sum1 += c[nt][2] + c[nt][3];
        }
        sum0 += __shfl_xor_sync(0xffffffff, sum0, 1);
        sum0 += __shfl_xor_sync(0xffffffff, sum0, 2);
        sum1 += __shfl_xor_sync(0xffffffff, sum1, 1);
        sum1 += __shfl_xor_sync(0xffffffff, sum1, 2);
        l0r = l0r * rsc0 + sum0;
        l1r = l1r * rsc1 + sum1;

        // ---- rescale O, then O += P V ----
#pragma unroll
        for (int nt = 0; nt < 8; nt++) {
            o[nt][0] *= rsc0; o[nt][1] *= rsc0;
            o[nt][2] *= rsc1; o[nt][3] *= rsc1;
        }
#pragma unroll
        for (int kk = 0; kk < 8; kk++) {
            uint32_t pah[4], pal[4];
            pah[0] = packsplit(c[2 * kk][0],     c[2 * kk][1],     pal[0]);
            pah[1] = packsplit(c[2 * kk][2],     c[2 * kk][3],     pal[1]);
            pah[2] = packsplit(c[2 * kk + 1][0], c[2 * kk + 1][1], pal[2]);
            pah[3] = packsplit(c[2 * kk + 1][2], c[2 * kk + 1][3], pal[3]);
#pragma unroll
            for (int nt = 0; nt < 8; nt++) {
                int a = (nt * 8 + g) * LDV + kk * 16 + tg * 2;
                uint32_t vh[2], vl[2];
                vh[0] = *(uint32_t*)(Vth + a);
                vh[1] = *(uint32_t*)(Vth + a + 8);
                vl[0] = *(uint32_t*)(Vtl + a);
                vl[1] = *(uint32_t*)(Vtl + a + 8);
                mma16816(o[nt], pah, vh);
                mma16816(o[nt], pal, vh);
                mma16816(o[nt], pah, vl);
            }
        }
        __syncthreads();
    }

    // ---- epilogue: O / l ----
    float inv0 = 1.f / l0r, inv1 = 1.f / l1r;
#pragma unroll
    for (int nt = 0; nt < 8; nt++) {
        int d = nt * 8 + tg * 2;
        *(float2*)(out + (base + (size_t)qi0 * DH) + d) =
            make_float2(o[nt][0] * inv0, o[nt][1] * inv0);
        *(float2*)(out + (base + (size_t)qi1 * DH) + d) =
            make_float2(o[nt][2] * inv1, o[nt][3] * inv1);
    }
}

// ============================================================================
// launch
// ============================================================================
extern "C" void kernel_launch(void* const* d_in, const int* in_sizes, int n_in,
                              void* d_out, int out_size)
{
    const float* x   = (const float*)d_in[0];   // [4,1024,1024]
    const float* Wq  = (const float*)d_in[1];   // [1024, 1024]
    const float* Wkv = (const float*)d_in[2];   // [1024, 2048]
    const float* pe  = (const float*)d_in[3];   // [1025, 64]
    float* out = (float*)d_out;                 // [4,16,1024,64]

    conv_x<<<(MROWS * DIMIN + 255) / 256, 256>>>(x);
    conv_wT<<<dim3(NPROJ / 32, DIMIN / 32), 256>>>(Wq, Wkv);
    conv_pe<<<(PE_PAD * DH + 255) / 256, 256>>>(pe);

    const int smem_proj = 4 * TILE_E * (int)sizeof(__nv_bfloat16);   // 57344
    cudaFuncSetAttribute(proj_mma, cudaFuncAttributeMaxDynamicSharedMemorySize, smem_proj);
    proj_mma<<<dim3(NPROJ / 128, MROWS / 128), 256, smem_proj>>>();

    const int smem_qp = 4 * TILE_E2 * (int)sizeof(__nv_bfloat16);    // 73728
    cudaFuncSetAttribute(qp_mma, cudaFuncAttributeMaxDynamicSharedMemorySize, smem_qp);
    qp_mma<<<dim3(9, 512), 256, smem_qp>>>();

    cudaFuncSetAttribute(attn_mma, cudaFuncAttributeMaxDynamicSharedMemorySize, SMEM_ATTN2);
    attn_mma<<<dim3(64, 8), 256, SMEM_ATTN2>>>(out);
}